// round 2
// baseline (speedup 1.0000x reference)
#include <cuda_runtime.h>
#include <cstdint>

// Problem constants
#define BB 2
#define DD 512
#define KK 32
#define NN 4096           // H*W
#define NB 64             // n per block (assign kernel)
#define DC 64             // d chunk (assign kernel)
#define NCHUNKS 8         // n splits for aggregation
#define ZSIZE (BB*DD*KK)  // 32768

// ---------- device scratch (no allocations allowed) ----------
__device__ unsigned long long g_A2[DD*KK];     // (s^2, s^2) packed f32x2, [d][k]
__device__ unsigned long long g_B2[DD*KK];     // (-2 s^2 c) duplicated,  [d][k]
__device__ float g_C[KK];                      // sum_d s^2 c^2
__device__ float g_S1part[(BB*NN/NB)*KK];      // per-block Q column sums (128 x 32)
__device__ float g_Mpart[NCHUNKS][BB*DD*KK];   // partial M = sum_n Q*x

// ---------- f32x2 helpers ----------
__device__ __forceinline__ unsigned long long pk2(float lo, float hi) {
    unsigned long long r;
    asm("mov.b64 %0, {%1,%2};" : "=l"(r) : "f"(lo), "f"(hi));
    return r;
}
__device__ __forceinline__ void upk2(unsigned long long v, float& lo, float& hi) {
    asm("mov.b64 {%0,%1}, %2;" : "=f"(lo), "=f"(hi) : "l"(v));
}
__device__ __forceinline__ unsigned long long fma2(unsigned long long a,
                                                   unsigned long long b,
                                                   unsigned long long c) {
    unsigned long long d;
    asm("fma.rn.f32x2 %0, %1, %2, %3;" : "=l"(d) : "l"(a), "l"(b), "l"(c));
    return d;
}

// ---------- kernel 1: coefficient prep ----------
// A[d,k] = s^2 ; Bc[d,k] = -2 s^2 c ; C[k] = sum_d s^2 c^2
__global__ __launch_bounds__(256) void prep_kernel(const float* __restrict__ scale,
                                                   const float* __restrict__ cw) {
    int k = blockIdx.x;
    int t = threadIdx.x;
    float csum = 0.f;
    for (int d = t; d < DD; d += 256) {
        float s  = scale[d*KK + k];
        float c  = cw[k*DD + d];
        float s2 = s*s;
        float bc = -2.f*s2*c;
        g_A2[d*KK + k] = pk2(s2, s2);
        g_B2[d*KK + k] = pk2(bc, bc);
        csum += s2*c*c;
    }
    __shared__ float red[256];
    red[t] = csum; __syncthreads();
    #pragma unroll
    for (int off = 128; off > 0; off >>= 1) {
        if (t < off) red[t] += red[t + off];
        __syncthreads();
    }
    if (t == 0) g_C[k] = red[0];
}

// ---------- kernel 2: E = dot(x^2,A)+dot(x,Bc)+C, softmax over K, write Q ----------
// grid 128 (64 n each), 256 threads. lane = k. Warps partition D (cross-warp
// partials reduced in smem). f32x2 packs n-pairs.
__global__ __launch_bounds__(256) void assign_kernel(const float* __restrict__ X,
                                                     float* __restrict__ out) {
    extern __shared__ unsigned char smraw[];
    float*              Xs = (float*)smraw;                          // [DC][NB] 16KB
    unsigned long long* As = (unsigned long long*)(smraw + 16*1024); // [DC*KK] 16KB
    unsigned long long* Bs = (unsigned long long*)(smraw + 32*1024); // 16KB
    float*              Ep = (float*)smraw;                          // alias: [8][NB][KK] 64KB
    float*              Ef = (float*)(smraw + 64*1024);              // [NB][KK] 8KB
    float*              s1s = (float*)(smraw + 72*1024);             // [KK]

    const int tid  = threadIdx.x;
    const int lane = tid & 31;
    const int w    = tid >> 5;
    const int n0   = blockIdx.x * NB;        // global over B*N
    const int b    = n0 >> 12;               // /4096
    const float* Xb = X + (size_t)b * DD * NN + (n0 & (NN - 1));

    unsigned long long acc[NB/2];
    #pragma unroll
    for (int i = 0; i < NB/2; i++) acc[i] = 0ull;

    for (int dc = 0; dc < DD; dc += DC) {
        // stage X tile [DC][NB] (coalesced float4)
        #pragma unroll
        for (int it = 0; it < 4; it++) {
            int idx = tid + it*256;          // 0..1023 float4s
            int r = idx >> 4, c4 = idx & 15;
            *(float4*)&Xs[r*NB + c4*4] =
                *(const float4*)(Xb + (size_t)(dc + r)*NN + c4*4);
        }
        // stage coefficients
        const float4* gA4 = (const float4*)(g_A2 + dc*KK);
        const float4* gB4 = (const float4*)(g_B2 + dc*KK);
        float4* As4 = (float4*)As; float4* Bs4 = (float4*)Bs;
        #pragma unroll
        for (int it = 0; it < 4; it++) {
            int idx = tid + it*256;          // 0..1023 float4s (=2048 ull each)
            As4[idx] = gA4[idx];
            Bs4[idx] = gB4[idx];
        }
        __syncthreads();
        // each warp takes d = dc + w, dc + w + 8, ...
        for (int dd = w; dd < DC; dd += 8) {
            unsigned long long a2 = As[dd*KK + lane];
            unsigned long long b2 = Bs[dd*KK + lane];
            const float* xr = &Xs[dd*NB];
            #pragma unroll
            for (int g = 0; g < 16; g++) {
                longlong2 xv = *reinterpret_cast<const longlong2*>(xr + g*4);
                unsigned long long x01 = (unsigned long long)xv.x;
                unsigned long long x23 = (unsigned long long)xv.y;
                unsigned long long t0 = fma2(a2, x01, b2);     // a*x + b
                acc[2*g]   = fma2(x01, t0, acc[2*g]);          // += x*(a*x+b)
                unsigned long long t1 = fma2(a2, x23, b2);
                acc[2*g+1] = fma2(x23, t1, acc[2*g+1]);
            }
        }
        __syncthreads();
    }

    // dump per-warp partials (aliases the staging buffers; all compute done)
    #pragma unroll
    for (int i = 0; i < NB/2; i++) {
        float lo, hi; upk2(acc[i], lo, hi);
        Ep[(w*NB + 2*i  )*KK + lane] = lo;
        Ep[(w*NB + 2*i+1)*KK + lane] = hi;
    }
    if (tid < KK) s1s[tid] = 0.f;
    __syncthreads();
    // reduce 8 warps
    for (int idx = tid; idx < NB*KK; idx += 256) {
        float s = Ep[idx];
        #pragma unroll
        for (int ww = 1; ww < 8; ww++) s += Ep[ww*NB*KK + idx];
        Ef[idx] = s;
    }
    __syncthreads();

    // softmax over k (lanes), warp w handles 8 n's
    float* Qout = out + ZSIZE;
    const float Ck = g_C[lane];
    float s1loc = 0.f;
    #pragma unroll
    for (int i = 0; i < 8; i++) {
        int n = w*8 + i;
        float arg = -0.5f * (Ef[n*KK + lane] + Ck);
        float m = arg;
        #pragma unroll
        for (int off = 16; off; off >>= 1) m = fmaxf(m, __shfl_xor_sync(~0u, m, off));
        float ex = __expf(arg - m);
        float ssum = ex;
        #pragma unroll
        for (int off = 16; off; off >>= 1) ssum += __shfl_xor_sync(~0u, ssum, off);
        float q = ex / ssum;
        Qout[(size_t)(n0 + n)*KK + lane] = q;
        s1loc += q;
    }
    atomicAdd(&s1s[lane], s1loc);   // smem only; global stays deterministic
    __syncthreads();
    if (w == 0) g_S1part[blockIdx.x*KK + lane] = s1s[lane];
}

// ---------- kernel 3: Mpart[nc][b,d,k] = sum_{n in chunk} Q[b,n,k] * X[b,d,n] ----------
// grid 128 = b(2) x dtile(8 of 64d) x nchunk(8 of 512n); 256 threads, lane=k,
// each warp owns 8 d rows; f32x2 packs n-pairs.
__global__ __launch_bounds__(256) void aggregate_kernel(const float* __restrict__ X,
                                                        const float* __restrict__ out) {
    __shared__ float Xs[64*64];   // 16KB
    __shared__ float Qs[64*KK];   // 8KB
    const int tid  = threadIdx.x;
    const int lane = tid & 31;
    const int w    = tid >> 5;
    const int idx  = blockIdx.x;
    const int b    = idx >> 6;
    const int dt   = (idx >> 3) & 7;
    const int nc   = idx & 7;
    const int d0   = dt*64;
    const int nb0  = nc*(NN/NCHUNKS);

    const float* Qb = out + ZSIZE + (size_t)b*NN*KK;
    const float* Xb = X + (size_t)b*DD*NN;

    unsigned long long acc[8];
    #pragma unroll
    for (int j = 0; j < 8; j++) acc[j] = 0ull;

    for (int s = 0; s < (NN/NCHUNKS)/64; s++) {   // 8 subtiles of 64 n
        int nbase = nb0 + s*64;
        #pragma unroll
        for (int it = 0; it < 4; it++) {
            int i2 = tid + it*256; int r = i2 >> 4, c4 = i2 & 15;
            *(float4*)&Xs[r*64 + c4*4] =
                *(const float4*)(Xb + (size_t)(d0 + r)*NN + nbase + c4*4);
        }
        #pragma unroll
        for (int it = 0; it < 2; it++) {
            int i2 = tid + it*256;
            *(float4*)&Qs[i2*4] = *(const float4*)(Qb + (size_t)nbase*KK + i2*4);
        }
        __syncthreads();
        #pragma unroll
        for (int g = 0; g < 16; g++) {   // 4 n per group
            float q0 = Qs[(4*g+0)*KK + lane];
            float q1 = Qs[(4*g+1)*KK + lane];
            float q2 = Qs[(4*g+2)*KK + lane];
            float q3 = Qs[(4*g+3)*KK + lane];
            unsigned long long q01 = pk2(q0, q1), q23 = pk2(q2, q3);
            #pragma unroll
            for (int j = 0; j < 8; j++) {
                longlong2 xv = *reinterpret_cast<const longlong2*>(&Xs[(w*8+j)*64 + 4*g]);
                acc[j] = fma2(q01, (unsigned long long)xv.x, acc[j]);
                acc[j] = fma2(q23, (unsigned long long)xv.y, acc[j]);
            }
        }
        __syncthreads();
    }
    #pragma unroll
    for (int j = 0; j < 8; j++) {
        float lo, hi; upk2(acc[j], lo, hi);
        g_Mpart[nc][((size_t)b*DD + d0 + w*8 + j)*KK + lane] = lo + hi;
    }
}

// ---------- kernel 4 (v2): Z = normalize_D( s*(M/S1 - c) ) ----------
// grid 2 (one per batch) x 1024 threads. lane = k (coalesced Mpart/scale/out),
// warp w owns d = w + 32*i. cw staged transposed into padded smem.
// All reductions are fixed-order smem trees -> deterministic.
__global__ __launch_bounds__(1024) void finalize_kernel(const float* __restrict__ scale,
                                                        const float* __restrict__ cw,
                                                        float* __restrict__ out) {
    extern __shared__ float fsm[];
    float* cwsh = fsm;                 // [512][33] transposed codewords
    float* red  = fsm + DD*33;         // [32][33]
    float* bcast = red + 32*33;        // [KK]

    const int b    = blockIdx.x;
    const int tid  = threadIdx.x;
    const int lane = tid & 31;         // k
    const int w    = tid >> 5;         // 0..31

    // stage cw [K][D] -> cwsh[d*33+k] (coalesced loads, conflict-free stores)
    #pragma unroll
    for (int j = 0; j < 16; j++) {
        int i = tid + j*1024;          // 0..16383
        int k = i >> 9, d = i & 511;
        cwsh[d*33 + k] = cw[i];
    }

    // S1: 64 partials per (b,k); thread (w,lane) grabs 2, tree-reduce over w
    float s1p = g_S1part[(b*64 + w)*KK + lane]
              + g_S1part[(b*64 + 32 + w)*KK + lane];
    red[w*33 + lane] = s1p;
    __syncthreads();
    if (w == 0) {
        float s = 0.f;
        #pragma unroll
        for (int i = 0; i < 32; i++) s += red[i*33 + lane];
        bcast[lane] = 1.f / s;
    }
    __syncthreads();
    const float inv_s1 = bcast[lane];

    // z = s*(M/S1 - c); accumulate sumsq over this thread's 16 d's
    float z[16];
    float ss = 0.f;
    #pragma unroll
    for (int i = 0; i < 16; i++) {
        int d = w + 32*i;
        size_t mi = ((size_t)b*DD + d)*KK + lane;
        float m = 0.f;
        #pragma unroll
        for (int c = 0; c < NCHUNKS; c++) m += g_Mpart[c][mi];
        float zz = scale[d*KK + lane] * (m*inv_s1 - cwsh[d*33 + lane]);
        z[i] = zz;
        ss += zz*zz;
    }
    __syncthreads();
    red[w*33 + lane] = ss;
    __syncthreads();
    if (w == 0) {
        float s = 0.f;
        #pragma unroll
        for (int i = 0; i < 32; i++) s += red[i*33 + lane];
        bcast[lane] = 1.f / sqrtf(s);
    }
    __syncthreads();
    const float invn = bcast[lane];
    #pragma unroll
    for (int i = 0; i < 16; i++) {
        int d = w + 32*i;
        out[((size_t)b*DD + d)*KK + lane] = z[i]*invn;
    }
}

extern "C" void kernel_launch(void* const* d_in, const int* in_sizes, int n_in,
                              void* d_out, int out_size) {
    const float* X     = (const float*)d_in[0];
    const float* cw    = (const float*)d_in[1];
    const float* scale = (const float*)d_in[2];
    float* out = (float*)d_out;

    const int SMEM_ASSIGN = 72*1024 + 128;
    cudaFuncSetAttribute(assign_kernel, cudaFuncAttributeMaxDynamicSharedMemorySize,
                         SMEM_ASSIGN);
    const int SMEM_FIN = (DD*33 + 32*33 + KK)*4;
    cudaFuncSetAttribute(finalize_kernel, cudaFuncAttributeMaxDynamicSharedMemorySize,
                         SMEM_FIN);

    prep_kernel<<<KK, 256>>>(scale, cw);
    assign_kernel<<<(BB*NN)/NB, 256, SMEM_ASSIGN>>>(X, out);
    aggregate_kernel<<<BB*8*NCHUNKS, 256>>>(X, out);
    finalize_kernel<<<BB, 1024, SMEM_FIN>>>(scale, cw, out);
}

// round 3
// speedup vs baseline: 1.2126x; 1.2126x over previous
#include <cuda_runtime.h>
#include <cstdint>

// Problem constants
#define BB 2
#define DD 512
#define KK 32
#define NN 4096           // H*W
#define NB 32             // n per block (assign kernel)
#define DC 64             // d chunk (assign kernel)
#define NCHUNKS 16        // n splits for aggregation
#define ZSIZE (BB*DD*KK)  // 32768

// ---------- device scratch (no allocations allowed) ----------
__device__ unsigned long long g_A2[DD*KK];     // (s^2, s^2) packed f32x2, [d][k]
__device__ unsigned long long g_B2[DD*KK];     // (-2 s^2 c) duplicated,  [d][k]
__device__ float g_C[KK];                      // sum_d s^2 c^2
__device__ float g_S1part[(BB*NN/NB)*KK];      // per-block Q column sums (256 x 32)
__device__ float g_Mpart[NCHUNKS][BB*DD*KK];   // partial M = sum_n Q*x
__device__ float g_SS[BB*16*KK];               // per-dtile sumsq partials

// ---------- f32x2 helpers ----------
__device__ __forceinline__ unsigned long long pk2(float lo, float hi) {
    unsigned long long r;
    asm("mov.b64 %0, {%1,%2};" : "=l"(r) : "f"(lo), "f"(hi));
    return r;
}
__device__ __forceinline__ void upk2(unsigned long long v, float& lo, float& hi) {
    asm("mov.b64 {%0,%1}, %2;" : "=f"(lo), "=f"(hi) : "l"(v));
}
__device__ __forceinline__ unsigned long long fma2(unsigned long long a,
                                                   unsigned long long b,
                                                   unsigned long long c) {
    unsigned long long d;
    asm("fma.rn.f32x2 %0, %1, %2, %3;" : "=l"(d) : "l"(a), "l"(b), "l"(c));
    return d;
}

// ---------- kernel 1: coefficient prep ----------
__global__ __launch_bounds__(256) void prep_kernel(const float* __restrict__ scale,
                                                   const float* __restrict__ cw) {
    int k = blockIdx.x;
    int t = threadIdx.x;
    float csum = 0.f;
    for (int d = t; d < DD; d += 256) {
        float s  = scale[d*KK + k];
        float c  = cw[k*DD + d];
        float s2 = s*s;
        float bc = -2.f*s2*c;
        g_A2[d*KK + k] = pk2(s2, s2);
        g_B2[d*KK + k] = pk2(bc, bc);
        csum += s2*c*c;
    }
    __shared__ float red[256];
    red[t] = csum; __syncthreads();
    #pragma unroll
    for (int off = 128; off > 0; off >>= 1) {
        if (t < off) red[t] += red[t + off];
        __syncthreads();
    }
    if (t == 0) g_C[k] = red[0];
}

// ---------- kernel 2: E-GEMM + softmax -> Q (NB=32 per block, grid 256) ----------
__global__ __launch_bounds__(256) void assign_kernel(const float* __restrict__ X,
                                                     float* __restrict__ out) {
    extern __shared__ unsigned char smraw[];
    float*              Xs = (float*)smraw;                          // [DC][NB] 8KB
    unsigned long long* As = (unsigned long long*)(smraw + 8*1024);  // 16KB
    unsigned long long* Bs = (unsigned long long*)(smraw + 24*1024); // 16KB
    float*              Ep = (float*)smraw;                          // alias [8][NB][KK] 32KB
    float*              Ef = (float*)(smraw + 40*1024);              // [NB][KK] 4KB
    float*              s1s = (float*)(smraw + 44*1024);             // [KK]

    const int tid  = threadIdx.x;
    const int lane = tid & 31;
    const int w    = tid >> 5;
    const int n0   = blockIdx.x * NB;        // global over B*N
    const int b    = n0 >> 12;
    const float* Xb = X + (size_t)b * DD * NN + (n0 & (NN - 1));

    unsigned long long acc[NB/2];
    #pragma unroll
    for (int i = 0; i < NB/2; i++) acc[i] = 0ull;

    for (int dc = 0; dc < DD; dc += DC) {
        // stage X tile [DC=64][NB=32] (512 float4)
        #pragma unroll
        for (int it = 0; it < 2; it++) {
            int idx = tid + it*256;
            int r = idx >> 3, c4 = idx & 7;
            *(float4*)&Xs[r*NB + c4*4] =
                *(const float4*)(Xb + (size_t)(dc + r)*NN + c4*4);
        }
        // stage coefficients (1024 float4 each)
        const float4* gA4 = (const float4*)(g_A2 + dc*KK);
        const float4* gB4 = (const float4*)(g_B2 + dc*KK);
        float4* As4 = (float4*)As; float4* Bs4 = (float4*)Bs;
        #pragma unroll
        for (int it = 0; it < 4; it++) {
            int idx = tid + it*256;
            As4[idx] = gA4[idx];
            Bs4[idx] = gB4[idx];
        }
        __syncthreads();
        // warp w handles d = dc+w, dc+w+8, ...
        for (int dd = w; dd < DC; dd += 8) {
            unsigned long long a2 = As[dd*KK + lane];
            unsigned long long b2 = Bs[dd*KK + lane];
            const float* xr = &Xs[dd*NB];
            #pragma unroll
            for (int g = 0; g < NB/4; g++) {
                longlong2 xv = *reinterpret_cast<const longlong2*>(xr + g*4);
                unsigned long long x01 = (unsigned long long)xv.x;
                unsigned long long x23 = (unsigned long long)xv.y;
                unsigned long long t0 = fma2(a2, x01, b2);     // a*x + b
                acc[2*g]   = fma2(x01, t0, acc[2*g]);          // += x*(a*x+b)
                unsigned long long t1 = fma2(a2, x23, b2);
                acc[2*g+1] = fma2(x23, t1, acc[2*g+1]);
            }
        }
        __syncthreads();
    }

    // per-warp partial dump (aliases staging)
    #pragma unroll
    for (int i = 0; i < NB/2; i++) {
        float lo, hi; upk2(acc[i], lo, hi);
        Ep[(w*NB + 2*i  )*KK + lane] = lo;
        Ep[(w*NB + 2*i+1)*KK + lane] = hi;
    }
    if (tid < KK) s1s[tid] = 0.f;
    __syncthreads();
    for (int idx = tid; idx < NB*KK; idx += 256) {
        float s = Ep[idx];
        #pragma unroll
        for (int ww = 1; ww < 8; ww++) s += Ep[ww*NB*KK + idx];
        Ef[idx] = s;
    }
    __syncthreads();

    // softmax over k (lanes); warp w handles 4 n
    float* Qout = out + ZSIZE;
    const float Ck = g_C[lane];
    float s1loc = 0.f;
    #pragma unroll
    for (int i = 0; i < NB/8; i++) {
        int n = w*(NB/8) + i;
        float arg = -0.5f * (Ef[n*KK + lane] + Ck);
        float m = arg;
        #pragma unroll
        for (int off = 16; off; off >>= 1) m = fmaxf(m, __shfl_xor_sync(~0u, m, off));
        float ex = __expf(arg - m);
        float ssum = ex;
        #pragma unroll
        for (int off = 16; off; off >>= 1) ssum += __shfl_xor_sync(~0u, ssum, off);
        float q = ex / ssum;
        Qout[(size_t)(n0 + n)*KK + lane] = q;
        s1loc += q;
    }
    atomicAdd(&s1s[lane], s1loc);   // smem only, per-block -> deterministic output
    __syncthreads();
    if (w == 0) g_S1part[blockIdx.x*KK + lane] = s1s[lane];
}

// ---------- kernel 3: Mpart[nc][b,d,k] = sum_{n in chunk} Q[b,n,k]*X[b,d,n] ----------
// grid 256 = b(2) x dtile(8 of 64d) x nchunk(16 of 256n)
__global__ __launch_bounds__(256) void aggregate_kernel(const float* __restrict__ X,
                                                        const float* __restrict__ out) {
    __shared__ float Xs[64*64];   // 16KB
    __shared__ float Qs[64*KK];   // 8KB
    const int tid  = threadIdx.x;
    const int lane = tid & 31;
    const int w    = tid >> 5;
    const int idx  = blockIdx.x;
    const int b    = idx >> 7;
    const int dt   = (idx >> 4) & 7;
    const int nc   = idx & 15;
    const int d0   = dt*64;
    const int nb0  = nc*(NN/NCHUNKS);

    const float* Qb = out + ZSIZE + (size_t)b*NN*KK;
    const float* Xb = X + (size_t)b*DD*NN;

    unsigned long long acc[8];
    #pragma unroll
    for (int j = 0; j < 8; j++) acc[j] = 0ull;

    #pragma unroll
    for (int s = 0; s < (NN/NCHUNKS)/64; s++) {   // 4 subtiles of 64 n
        int nbase = nb0 + s*64;
        #pragma unroll
        for (int it = 0; it < 4; it++) {
            int i2 = tid + it*256; int r = i2 >> 4, c4 = i2 & 15;
            *(float4*)&Xs[r*64 + c4*4] =
                *(const float4*)(Xb + (size_t)(d0 + r)*NN + nbase + c4*4);
        }
        #pragma unroll
        for (int it = 0; it < 2; it++) {
            int i2 = tid + it*256;
            *(float4*)&Qs[i2*4] = *(const float4*)(Qb + (size_t)nbase*KK + i2*4);
        }
        __syncthreads();
        #pragma unroll
        for (int g = 0; g < 16; g++) {   // 4 n per group
            float q0 = Qs[(4*g+0)*KK + lane];
            float q1 = Qs[(4*g+1)*KK + lane];
            float q2 = Qs[(4*g+2)*KK + lane];
            float q3 = Qs[(4*g+3)*KK + lane];
            unsigned long long q01 = pk2(q0, q1), q23 = pk2(q2, q3);
            #pragma unroll
            for (int j = 0; j < 8; j++) {
                longlong2 xv = *reinterpret_cast<const longlong2*>(&Xs[(w*8+j)*64 + 4*g]);
                acc[j] = fma2(q01, (unsigned long long)xv.x, acc[j]);
                acc[j] = fma2(q23, (unsigned long long)xv.y, acc[j]);
            }
        }
        __syncthreads();
    }
    #pragma unroll
    for (int j = 0; j < 8; j++) {
        float lo, hi; upk2(acc[j], lo, hi);
        g_Mpart[nc][((size_t)b*DD + d0 + w*8 + j)*KK + lane] = lo + hi;
    }
}

// ---------- kernel 4a: unnormalized Z into out, per-tile sumsq partials ----------
// grid 32 = b(2) x dtile(16 of 32d); 1024 threads; warp w owns d = d0+w, lane = k.
__global__ __launch_bounds__(1024) void finalize1_kernel(const float* __restrict__ scale,
                                                         const float* __restrict__ cw,
                                                         float* __restrict__ out) {
    __shared__ float red[32*33];
    __shared__ float cwsh[32*33];
    __shared__ float bcast[KK];

    const int b    = blockIdx.x >> 4;
    const int dt   = blockIdx.x & 15;
    const int d0   = dt*32;
    const int tid  = threadIdx.x;
    const int lane = tid & 31;         // k
    const int w    = tid >> 5;         // 0..31

    // stage cw: warp w loads row k=w, d = d0+lane -> cwsh[k][d_local]
    cwsh[w*33 + lane] = cw[w*DD + d0 + lane];

    // S1 reduce: 128 partials per (b,k); thread sums 4 (fixed order), tree over w
    float s1p = 0.f;
    #pragma unroll
    for (int j = 0; j < 4; j++)
        s1p += g_S1part[(b*128 + w + 32*j)*KK + lane];
    red[w*33 + lane] = s1p;
    __syncthreads();
    if (w == 0) {
        float s = 0.f;
        #pragma unroll
        for (int i = 0; i < 32; i++) s += red[i*33 + lane];
        bcast[lane] = 1.f / s;
    }
    __syncthreads();
    const float inv_s1 = bcast[lane];

    // m = sum of 16 Mpart chunks (coalesced, MLP=16)
    const int d = d0 + w;
    const size_t mi = ((size_t)b*DD + d)*KK + lane;
    float m = 0.f;
    #pragma unroll
    for (int c = 0; c < NCHUNKS; c++) m += g_Mpart[c][mi];

    float z = scale[d*KK + lane] * (m*inv_s1 - cwsh[lane*33 + w]);
    out[mi] = z;                       // unnormalized; part2 rescales in place

    __syncthreads();
    red[w*33 + lane] = z*z;
    __syncthreads();
    if (w == 0) {
        float s = 0.f;
        #pragma unroll
        for (int i = 0; i < 32; i++) s += red[i*33 + lane];
        g_SS[(b*16 + dt)*KK + lane] = s;
    }
}

// ---------- kernel 4b: rescale Z by 1/sqrt(sum_d z^2) ----------
// grid 8 = b(2) x quarter(4); 1024 threads; 128 d per block.
__global__ __launch_bounds__(1024) void finalize2_kernel(float* __restrict__ out) {
    __shared__ float bcast[KK];
    const int b   = blockIdx.x >> 2;
    const int q   = blockIdx.x & 3;
    const int tid = threadIdx.x;
    const int lane = tid & 31;
    const int w    = tid >> 5;

    if (tid < KK) {
        float s = 0.f;
        #pragma unroll
        for (int i = 0; i < 16; i++) s += g_SS[(b*16 + i)*KK + tid];
        bcast[tid] = 1.f / sqrtf(s);
    }
    __syncthreads();
    const float invn = bcast[lane];
    #pragma unroll
    for (int j = 0; j < 4; j++) {
        int d = q*128 + w*4 + j;
        out[((size_t)b*DD + d)*KK + lane] *= invn;
    }
}

extern "C" void kernel_launch(void* const* d_in, const int* in_sizes, int n_in,
                              void* d_out, int out_size) {
    const float* X     = (const float*)d_in[0];
    const float* cw    = (const float*)d_in[1];
    const float* scale = (const float*)d_in[2];
    float* out = (float*)d_out;

    const int SMEM_ASSIGN = 44*1024 + 128;
    cudaFuncSetAttribute(assign_kernel, cudaFuncAttributeMaxDynamicSharedMemorySize,
                         SMEM_ASSIGN);

    prep_kernel<<<KK, 256>>>(scale, cw);
    assign_kernel<<<(BB*NN)/NB, 256, SMEM_ASSIGN>>>(X, out);
    aggregate_kernel<<<BB*8*NCHUNKS, 256>>>(X, out);
    finalize1_kernel<<<BB*16, 1024>>>(scale, cw, out);
    finalize2_kernel<<<BB*4, 1024>>>(out);
}